// round 15
// baseline (speedup 1.0000x reference)
#include <cuda_runtime.h>
#include <math.h>
#include <stdint.h>

#define FULLM 0xffffffffu
#define BMAX 64
#define TMAX 1000
#define UPAD 256
#define NSLOT 5
#define STGB 16384u
#define LN2D 0.6931471805599453

typedef unsigned long long ull;

// Scratch (allocation-free rule: __device__ globals).
__device__ float g_loss[BMAX];
__device__ float g_logZ[BMAX * TMAX];
__device__ int   g_done;
__device__ __align__(128) float g_r[(size_t)BMAX * TMAX * UPAD];  // 64 MB

// ---- f32x2 packed helpers (Blackwell sm_103a) ------------------------------
__device__ __forceinline__ ull addx2(ull a, ull b) {
    ull r; asm("add.rn.f32x2 %0, %1, %2;" : "=l"(r) : "l"(a), "l"(b)); return r;
}
__device__ __forceinline__ ull mulx2(ull a, ull b) {
    ull r; asm("mul.rn.f32x2 %0, %1, %2;" : "=l"(r) : "l"(a), "l"(b)); return r;
}
__device__ __forceinline__ ull fma2(ull a, ull b, ull c) {
    ull r; asm("fma.rn.f32x2 %0, %1, %2, %3;"
               : "=l"(r) : "l"(a), "l"(b), "l"(c)); return r;
}
__device__ __forceinline__ ull packx2(float lo, float hi) {
    ull r; asm("mov.b64 %0, {%1, %2};" : "=l"(r) : "f"(lo), "f"(hi)); return r;
}
__device__ __forceinline__ float lox2(ull v) {
    float a, b; asm("mov.b64 {%0, %1}, %2;" : "=f"(a), "=f"(b) : "l"(v)); return a;
}
__device__ __forceinline__ float hix2(ull v) {
    float a, b; asm("mov.b64 {%0, %1}, %2;" : "=f"(a), "=f"(b) : "l"(v)); return b;
}
__device__ __forceinline__ uint32_t smem_u32(const void* p) {
    uint32_t a;
    asm("{.reg .u64 t; cvta.to.shared.u64 t, %1; cvt.u32.u64 %0, t;}"
        : "=r"(a) : "l"(p));
    return a;
}
__device__ __forceinline__ ulonglong2 lds128(uint32_t a) {
    ulonglong2 v;
    asm("ld.shared.v2.u64 {%0, %1}, [%2];" : "=l"(v.x), "=l"(v.y) : "r"(a));
    return v;
}
__device__ __forceinline__ void mbar_wait(uint32_t bar, int parity) {
    asm volatile(
        "{\n\t.reg .pred P;\n"
        "W%=:\n\t"
        "mbarrier.try_wait.parity.shared.b64 P, [%0], %1;\n\t"
        "@!P bra W%=;\n\t}"
        :: "r"(bar), "r"(parity) : "memory");
}
__device__ __forceinline__ void tma_fill(uint32_t dst, const float* src,
                                         uint32_t bar, uint32_t bytes) {
    asm volatile("mbarrier.arrive.expect_tx.shared.b64 _, [%0], %1;"
                 :: "r"(bar), "r"(bytes) : "memory");
    asm volatile(
        "cp.async.bulk.shared::cta.global.mbarrier::complete_tx::bytes "
        "[%0], [%1], %2, [%3];"
        :: "r"(dst), "l"(src), "r"(bytes), "r"(bar) : "memory");
}

// ---------------------------------------------------------------------------
// Phase 1: r[b,t,u] = exp(x+1) (masked for u>=tl); logZ = log1p(sum r) - 1.
// GROUPED store: float4 q covers r-columns 4q..4q+3 ordered (v0,v2,v1,v3),
// so one LDS.128 gives scan lane (w,l) (q=32w+l) its two stride-2 pairs.
// ---------------------------------------------------------------------------
__global__ void __launch_bounds__(256)
fsloss_prep(const float* __restrict__ attn, const int* __restrict__ text_lens,
            int B, int T, int U)
{
    if (blockIdx.x == 0 && threadIdx.x == 0) g_done = 0;

    const int gw   = (blockIdx.x * blockDim.x + threadIdx.x) >> 5;
    const int lane = threadIdx.x & 31;
    if (gw >= B * T) return;
    const int b  = gw / T;
    const int tl = text_lens[b];
    const int u0 = 8 * lane;

    const float2* x2 = (const float2*)(attn + (size_t)gw * U) + 4 * lane;
    float v[8];
    #pragma unroll
    for (int j = 0; j < 4; ++j) {
        float2 d = make_float2(0.f, 0.f);
        if (u0 + 2 * j + 1 < U) d = __ldg(&x2[j]);
        v[2 * j]     = d.x;
        v[2 * j + 1] = d.y;
    }
    float s = 0.f;
    #pragma unroll
    for (int k = 0; k < 8; ++k) {
        float e = (u0 + k < tl) ? __expf(v[k] + 1.f) : 0.f;  // r = exp(x+1)
        v[k] = e;
        s += e;
    }
    #pragma unroll
    for (int off = 16; off; off >>= 1) s += __shfl_xor_sync(FULLM, s, off);
    if (lane == 0) g_logZ[gw] = __logf(s + 1.f) - 1.f;

    float4* dst = (float4*)(g_r + (size_t)gw * UPAD);
    dst[2 * lane]     = make_float4(v[0], v[2], v[1], v[3]);
    dst[2 * lane + 1] = make_float4(v[4], v[6], v[5], v[7]);
}

// renorm: exponent from SUM of the lane's 8 values (upper bound on max).
#define RENORM(ISB)                                                           \
    do {                                                                      \
        ull sE_ = addx2(E[0], E[1]);                                          \
        ull sO_ = addx2(O[0], O[1]);                                          \
        ull sA_ = addx2(sE_, sO_);                                            \
        float ms_ = lox2(sA_) + hix2(sA_);                                    \
        bool nz_ = (ms_ > 0.f);                                               \
        if (nz_) {                                                            \
            int Ee_ = (int)((__float_as_uint(ms_) >> 23) & 255u);             \
            float sc_ = __uint_as_float((unsigned)(254 - Ee_) << 23);         \
            ull SC_ = packx2(sc_, sc_);                                       \
            E[0] = mulx2(E[0], SC_); E[1] = mulx2(E[1], SC_);                 \
            O[0] = mulx2(O[0], SC_); O[1] = mulx2(O[1], SC_);                 \
            G += Ee_ - 127;                                                   \
        }                                                                     \
        int val_ = (G << 1) | (nz_ ? 1 : 0);                                  \
        int up_  = __shfl_up_sync(FULLM, val_, 1);                            \
        int Gup_ = up_ >> 1;                                                  \
        if (!nz_) { if (lane > 0) G = Gup_; else if (ISB) G = g_cur; }        \
        int D_ = Gup_ - G; if (D_ > 127) D_ = 127;                            \
        f = (lane == 0 || !(up_ & 1) || D_ < -126) ? 0.f                      \
            : __uint_as_float((unsigned)(D_ + 127) << 23);                    \
        if (ISB) {                                                            \
            int Db_ = g_cur - G; if (Db_ > 127) Db_ = 127;                    \
            fB = (Db_ < -126) ? 0.f                                           \
                 : __uint_as_float((unsigned)(Db_ + 127) << 23);              \
        }                                                                     \
    } while (0)

#define DO_CAPTURE()                                                          \
    do {                                                                      \
        const int sb_ = 256 * w + 8 * lane;                                   \
        if (sb_     == S) fincap += lox2(E[0]);                               \
        if (sb_ + 2 == S) fincap += lox2(E[1]);                               \
        if (sb_ + 4 == S) fincap += hix2(E[0]);                               \
        if (sb_ + 6 == S) fincap += hix2(E[1]);                               \
        if (sb_ + 1 == S - 1) fincap += lox2(O[0]);                           \
        if (sb_ + 3 == S - 1) fincap += lox2(O[1]);                           \
        if (sb_ + 5 == S - 1) fincap += hix2(O[0]);                           \
        if (sb_ + 7 == S - 1) fincap += hix2(O[1]);                           \
        Gcap = G;                                                             \
    } while (0)

// one 16-step block; RENORM EVERY 4 STEPS (r=3,7,11 + block end) so the
// frontier (2 states/step) crosses at most ONE 8-state lane per window —
// the same invariant the proven 16-state/renorm-8 kernel relies on.
// ISB=0: warp A (states 0..255, block t, exports boundary);
// ISB=1: warp B (states 256..511, block t-1, imports boundary).
// bring_[r] = b[255] BEFORE step r; exports at r=3,7,11 are post-renorm, so
// bring_[4w..4w+3] are at scale sg[k&1][w]; B switches fB at its own renorms.
#define BLOCK_BODY(ISB)                                                       \
    do {                                                                      \
        const int k_ = (ISB) ? (t - 1) : t;                                   \
        int rb_ = 16 * k_; if (rb_ > T - 16) rb_ = T - 16;                    \
        const uint32_t stg_ = sdyn_a + (uint32_t)(k_ % NSLOT) * STGB          \
                            + (uint32_t)(16 * k_ - rb_) * 1024u + grp16;      \
        float* bring_ = sbound[k_ & 1];                                       \
        const bool tail_ = (k_ == nblk - 1);                                  \
        const int nlast_ = tail_ ? rem : 15;                                  \
        if (!(ISB)) {                                                         \
            if (lane == 31) { sg[k_ & 1][0] = G; bring_[0] = hix2(O[1]); }    \
        } else {                                                              \
            g_cur = sg[k_ & 1][0];                                            \
            int Db_ = g_cur - G; if (Db_ > 127) Db_ = 127;                    \
            fB = (Db_ < -126) ? 0.f                                           \
                 : __uint_as_float((unsigned)(Db_ + 127) << 23);              \
        }                                                                     \
        _Pragma("unroll")                                                     \
        for (int r = 0; r < 16; ++r) {                                        \
            ulonglong2 R_ = lds128(stg_ + (uint32_t)r * 1024u);               \
            float pv = prevS;                                                 \
            if ((ISB) && lane == 0) pv = bring_[r] * fB;                      \
            float o1lo = lox2(O[1]);                                          \
            ull h1 = mulx2(R_.y, O[1]);                                       \
            ull S1 = addx2(E[1], O[0]);                                       \
            ull O1n = fma2(R_.y, S1, h1);                                     \
            float raw = __shfl_up_sync(FULLM, hix2(O1n), 1);                  \
            ull h0 = mulx2(R_.x, O[0]);                                       \
            ull Osh0 = packx2(pv, o1lo);                                      \
            ull S0 = addx2(E[0], Osh0);                                       \
            O[0] = fma2(R_.x, S0, h0);                                        \
            E[0] = S0; E[1] = S1; O[1] = O1n;                                 \
            prevS = raw * f;                                                  \
            if (tail_ && r == nlast_) { DO_CAPTURE(); break; }                \
            if ((r & 3) == 3 && r < 15) {                                     \
                if (ISB) g_cur = sg[k_ & 1][(r >> 2) + 1];                    \
                RENORM(ISB);                                                  \
                if (!(ISB)) {                                                 \
                    if (lane == 31) sg[k_ & 1][(r >> 2) + 1] = G;             \
                }                                                             \
                prevS = __shfl_up_sync(FULLM, hix2(O[1]), 1) * f;             \
            }                                                                 \
            if (!(ISB) && r < 15) {                                           \
                if (lane == 31) bring_[r + 1] = hix2(O[1]);                   \
            }                                                                 \
        }                                                                     \
        if (!tail_) {                                                         \
            RENORM(ISB);                                                      \
            prevS = __shfl_up_sync(FULLM, hix2(O[1]), 1) * f;                 \
        }                                                                     \
    } while (0)

// ---------------------------------------------------------------------------
// Phase 2: TWO warps per batch. A owns states 0..255, B owns 256..511, B one
// block behind A; boundary scalar per step via smem ring with exact pow2
// scale conversion. TMA -> 5-slot x 16KB dynamic-smem ring, A-managed.
// ---------------------------------------------------------------------------
__global__ void __launch_bounds__(64)
fsloss_scan(const int* __restrict__ text_lens, const int* __restrict__ mel_lens,
            int T, float* __restrict__ out)
{
    extern __shared__ unsigned char sdyn[];
    __shared__ unsigned long long smbar[NSLOT];
    __shared__ float  sbound[2][16];
    __shared__ int    sg[2][4];
    __shared__ double sred[2], szs[2];

    const int tid = threadIdx.x, w = tid >> 5, lane = tid & 31;
    const int b  = blockIdx.x;
    const int tl = text_lens[b], ml = mel_lens[b];
    const int S  = 2 * tl, mlm1 = ml - 1;
    const int Bn = gridDim.x;

    const uint32_t sdyn_a = smem_u32(sdyn);
    const uint32_t mbar_a = smem_u32(smbar);
    const float*   src    = g_r + (size_t)b * T * UPAD;
    const uint32_t grp16  = (uint32_t)(32 * w + lane) * 16u;

    const int full = mlm1 >> 4, rem = mlm1 & 15, nblk = full + 1;

    if (tid == 0) {
        #pragma unroll
        for (int s = 0; s < NSLOT; ++s)
            asm volatile("mbarrier.init.shared.b64 [%0], 1;"
                         :: "r"(mbar_a + 8u * s) : "memory");
        int nf = nblk < 3 ? nblk : 3;
        for (int s = 0; s < nf; ++s) {
            int rb = 16 * s; if (rb > T - 16) rb = T - 16;
            tma_fill(sdyn_a + s * STGB, src + (size_t)rb * UPAD,
                     mbar_a + 8u * s, STGB);
        }
    }
    __syncthreads();

    ull E[2] = {0ull, 0ull}, O[2] = {0ull, 0ull};
    if (tid == 0) E[0] = packx2(1.f, 0.f);     // state 0 = 1 (warp A lane 0)
    int   G = 0, Gcap = 0, g_cur = 0;
    float fincap = 0.f;
    float f = (lane == 0) ? 0.f : 1.f;
    float fB = 1.f, prevS = 0.f;

    for (int t = 0; t <= nblk; ++t) {
        if (w == 0) {
            if (t < nblk) {
                mbar_wait(mbar_a + 8u * (t % NSLOT), (t / NSLOT) & 1);
                if (lane == 0 && t + 3 < nblk) {
                    int k3 = t + 3;
                    int rb = 16 * k3; if (rb > T - 16) rb = T - 16;
                    tma_fill(sdyn_a + (uint32_t)(k3 % NSLOT) * STGB,
                             src + (size_t)rb * UPAD,
                             mbar_a + 8u * (k3 % NSLOT), STGB);
                }
                BLOCK_BODY(0);
            }
        } else {
            if (t >= 1) BLOCK_BODY(1);
        }
        __syncthreads();
    }

    // per-warp lse over lanes (each warp's captures share that warp's timeline)
    double lv = (fincap > 0.f)
        ? (log((double)fincap) + (double)Gcap * LN2D) : -1e300;
    double mx = lv;
    #pragma unroll
    for (int off = 16; off; off >>= 1)
        mx = fmax(mx, __shfl_xor_sync(FULLM, mx, off));
    double ex = (lv > -1e299) ? exp(lv - mx) : 0.0;
    #pragma unroll
    for (int off = 16; off; off >>= 1)
        ex += __shfl_xor_sync(FULLM, ex, off);
    if (lane == 0)
        sred[w] = (mx > -1e299) ? (mx + log(ex)) : -1e300;

    // Zsum split across both warps
    const float* lz = g_logZ + (size_t)b * T;
    double zp = 0.0;
    for (int i = tid; i < ml; i += 64) zp += (double)__ldg(&lz[i]);
    #pragma unroll
    for (int off = 16; off; off >>= 1)
        zp += __shfl_xor_sync(FULLM, zp, off);
    if (lane == 0) szs[w] = zp;
    __syncthreads();

    if (tid == 0) {
        double zs = szs[0] + szs[1];
        double a = sred[0], c = sred[1];
        double m2 = fmax(a, c);
        float loss = 0.f;
        if (m2 > -1e299) {
            double e2 = ((a > -1e299) ? exp(a - m2) : 0.0)
                      + ((c > -1e299) ? exp(c - m2) : 0.0);
            double fin = (m2 + log(e2)) - (double)ml - zs;
            loss = (float)(-fin / (double)tl);
        }
        g_loss[b] = loss;
        __threadfence();
        int ticket = atomicAdd(&g_done, 1);
        if (ticket == Bn - 1) {            // last CTA reduces (fixed order)
            float s = 0.f;
            for (int i = 0; i < Bn; ++i) s += g_loss[i];
            out[0] = s / (float)Bn;
        }
    }
}

extern "C" void kernel_launch(void* const* d_in, const int* in_sizes, int n_in,
                              void* d_out, int out_size)
{
    const float* attn = (const float*)d_in[0];
    const int*   tl   = (const int*)d_in[1];
    const int*   ml   = (const int*)d_in[2];
    int B = in_sizes[1];
    const int U = 250;
    int T = in_sizes[0] / (B * U);

    cudaFuncSetAttribute(fsloss_scan,
                         cudaFuncAttributeMaxDynamicSharedMemorySize,
                         NSLOT * (int)STGB);

    int rows = B * T;
    fsloss_prep<<<(rows * 32 + 255) / 256, 256>>>(attn, tl, B, T, U);
    fsloss_scan<<<B, 64, NSLOT * STGB>>>(tl, ml, T, (float*)d_out);
}

// round 16
// speedup vs baseline: 1.2699x; 1.2699x over previous
#include <cuda_runtime.h>
#include <math.h>
#include <stdint.h>

#define FULLM 0xffffffffu
#define BMAX 64
#define NSLOT 5
#define STGB 16384u            // 16 rows x 1KB per stage
#define NPREP 8                // producer warps
#define LN2D 0.6931471805599453

typedef unsigned long long ull;

// Scratch (allocation-free rule: __device__ globals).
__device__ float g_loss[BMAX];
__device__ int   g_done = 0;   // reset by last CTA each launch

// ---- f32x2 packed helpers (Blackwell sm_103a) ------------------------------
__device__ __forceinline__ ull addx2(ull a, ull b) {
    ull r; asm("add.rn.f32x2 %0, %1, %2;" : "=l"(r) : "l"(a), "l"(b)); return r;
}
__device__ __forceinline__ ull mulx2(ull a, ull b) {
    ull r; asm("mul.rn.f32x2 %0, %1, %2;" : "=l"(r) : "l"(a), "l"(b)); return r;
}
__device__ __forceinline__ ull packx2(float lo, float hi) {
    ull r; asm("mov.b64 %0, {%1, %2};" : "=l"(r) : "f"(lo), "f"(hi)); return r;
}
__device__ __forceinline__ float lox2(ull v) {
    float a, b; asm("mov.b64 {%0, %1}, %2;" : "=f"(a), "=f"(b) : "l"(v)); return a;
}
__device__ __forceinline__ float hix2(ull v) {
    float a, b; asm("mov.b64 {%0, %1}, %2;" : "=f"(a), "=f"(b) : "l"(v)); return b;
}
__device__ __forceinline__ uint32_t smem_u32(const void* p) {
    uint32_t a;
    asm("{.reg .u64 t; cvta.to.shared.u64 t, %1; cvt.u32.u64 %0, t;}"
        : "=r"(a) : "l"(p));
    return a;
}
__device__ __forceinline__ ulonglong2 lds128(uint32_t a) {
    ulonglong2 v;
    asm("ld.shared.v2.u64 {%0, %1}, [%2];" : "=l"(v.x), "=l"(v.y) : "r"(a));
    return v;
}
__device__ __forceinline__ void mbar_wait(uint32_t bar, int parity) {
    asm volatile(
        "{\n\t.reg .pred P;\n"
        "W%=:\n\t"
        "mbarrier.try_wait.parity.shared.b64 P, [%0], %1;\n\t"
        "@!P bra W%=;\n\t}"
        :: "r"(bar), "r"(parity) : "memory");
}
__device__ __forceinline__ void mbar_arrive(uint32_t bar) {
    asm volatile("mbarrier.arrive.shared.b64 _, [%0];" :: "r"(bar) : "memory");
}

// renorm: exponent from SUM of the lane's 16 values (upper bound on max).
#define FS_RENORM()                                                           \
    do {                                                                      \
        ull sE = addx2(addx2(E[0], E[1]), addx2(E[2], E[3]));                 \
        ull sO = addx2(addx2(O[0], O[1]), addx2(O[2], O[3]));                 \
        ull sA = addx2(sE, sO);                                               \
        float msum = lox2(sA) + hix2(sA);                                     \
        bool nz = (msum > 0.f);                                               \
        if (nz) {                                                             \
            int Ee = (int)((__float_as_uint(msum) >> 23) & 255u);             \
            float sc = __uint_as_float((unsigned)(254 - Ee) << 23);           \
            ull SC = packx2(sc, sc);                                          \
            E[0] = mulx2(E[0], SC); E[1] = mulx2(E[1], SC);                   \
            E[2] = mulx2(E[2], SC); E[3] = mulx2(E[3], SC);                   \
            O[0] = mulx2(O[0], SC); O[1] = mulx2(O[1], SC);                   \
            O[2] = mulx2(O[2], SC); O[3] = mulx2(O[3], SC);                   \
            G += Ee - 127;                                                    \
        }                                                                     \
        int val = (G << 1) | (nz ? 1 : 0);                                    \
        int up  = __shfl_up_sync(FULLM, val, 1);                              \
        int Gup = up >> 1;                                                    \
        if (!nz && lane > 0) G = Gup;                                         \
        int D = Gup - G;                                                      \
        if (D > 127) D = 127;                                                 \
        f = (lane == 0 || !(up & 1) || D < -126) ? 0.f                        \
            : __uint_as_float((unsigned)(D + 127) << 23);                     \
    } while (0)

#define FS_CAPTURE()                                                          \
    do {                                                                      \
        _Pragma("unroll")                                                     \
        for (int k = 0; k < 8; ++k) {                                         \
            float ek = (k < 4) ? lox2(E[k]) : hix2(E[k - 4]);                 \
            float ok = (k < 4) ? lox2(O[k]) : hix2(O[k - 4]);                 \
            int se_ = 16 * lane + 2 * k;                                      \
            if (se_ == S)     fincap += ek;                                   \
            if (se_ == S - 2) fincap += ok;                                   \
        }                                                                     \
        Gcap = G;                                                             \
    } while (0)

// scan step: lane holds E[j]=(e[j],e[j+4]), O[j]=(o[j],o[j+4]) (16 states).
__device__ __forceinline__ void stepP(ull E[4], ull O[4],
                                      ulonglong2 Rlo, ulonglong2 Rhi,
                                      float prevS, float& rawNext)
{
    float o3lo = lox2(O[3]);
    ull S3 = addx2(E[3], O[2]);
    ull T3 = addx2(O[3], S3);
    ull O3n = mulx2(Rhi.y, T3);
    rawNext = __shfl_up_sync(FULLM, hix2(O3n), 1);
    ull S2 = addx2(E[2], O[1]);
    ull T2 = addx2(O[2], S2);
    O[2] = mulx2(Rhi.x, T2); E[2] = S2;
    ull S1 = addx2(E[1], O[0]);
    ull T1 = addx2(O[1], S1);
    O[1] = mulx2(Rlo.y, T1); E[1] = S1;
    ull Osh0 = packx2(prevS, o3lo);
    ull S0 = addx2(E[0], Osh0);
    ull T0 = addx2(O[0], S0);
    O[0] = mulx2(Rlo.x, T0); E[0] = S0;
    O[3] = O3n; E[3] = S3;
}

__device__ __forceinline__ void stepS(ull E[4], ull O[4],
                                      ulonglong2 Rlo, ulonglong2 Rhi, float f)
{
    float prev = __shfl_up_sync(FULLM, hix2(O[3]), 1) * f;
    float o3lo = lox2(O[3]);
    ull S3 = addx2(E[3], O[2]); ull T3 = addx2(O[3], S3);
    O[3] = mulx2(Rhi.y, T3); E[3] = S3;
    ull S2 = addx2(E[2], O[1]); ull T2 = addx2(O[2], S2);
    O[2] = mulx2(Rhi.x, T2); E[2] = S2;
    ull S1 = addx2(E[1], O[0]); ull T1 = addx2(O[1], S1);
    O[1] = mulx2(Rlo.y, T1); E[1] = S1;
    ull Osh0 = packx2(prev, o3lo);
    ull S0 = addx2(E[0], Osh0); ull T0 = addx2(O[0], S0);
    O[0] = mulx2(Rlo.x, T0); E[0] = S0;
}

// ---------------------------------------------------------------------------
// Fused kernel: one CTA per batch. 8 producer warps compute r = exp(x+1) rows
// straight into a 5-stage x 16KB smem ring (interleaved layout) and accumulate
// sum(logZ); 1 consumer warp runs the proven single-warp blocked-FP scan.
// Full barriers: count 8 (one arrive per producer warp / stage). Empty: 1.
// ---------------------------------------------------------------------------
__global__ void __launch_bounds__(288)
fsloss_fused(const float* __restrict__ attn,
             const int* __restrict__ text_lens,
             const int* __restrict__ mel_lens,
             int T, int U, float* __restrict__ out)
{
    extern __shared__ unsigned char sdyn[];
    __shared__ ull    sfull[NSLOT], sempty[NSLOT];
    __shared__ double szs[NPREP];

    const int tid = threadIdx.x, w = tid >> 5, lane = tid & 31;
    const int b  = blockIdx.x;
    const int tl = text_lens[b], ml = mel_lens[b];
    const int S  = 2 * tl, mlm1 = ml - 1;
    const int Bn = gridDim.x;
    const int full = mlm1 >> 4, rem = mlm1 & 15;   // full >= 37 (ml >= 600)

    const uint32_t sdyn_a  = smem_u32(sdyn);
    const uint32_t full_a  = smem_u32(sfull);
    const uint32_t empty_a = smem_u32(sempty);

    if (tid == 0) {
        #pragma unroll
        for (int s = 0; s < NSLOT; ++s) {
            asm volatile("mbarrier.init.shared.b64 [%0], %1;"
                         :: "r"(full_a + 8u * s), "r"(NPREP) : "memory");
            asm volatile("mbarrier.init.shared.b64 [%0], 1;"
                         :: "r"(empty_a + 8u * s) : "memory");
        }
    }
    __syncthreads();

    if (w < NPREP) {
        // ---------------- producer warp w: rows == w (mod 8) ----------------
        const float* xb = attn + (size_t)b * T * U;
        double zacc = 0.0;
        int slot = 0, rnd = 0;
        for (int s = 0; s <= full; ++s) {
            if (rnd) mbar_wait(empty_a + 8u * slot, (rnd - 1) & 1);
            unsigned char* stg = sdyn + (size_t)slot * STGB;
            #pragma unroll
            for (int h = 0; h < 2; ++h) {
                const int row = 16 * s + 8 * h + w;
                if (row < T) {
                    const int u0 = 8 * lane;
                    const float2* x2 =
                        (const float2*)(xb + (size_t)row * U) + 4 * lane;
                    float v[8];
                    #pragma unroll
                    for (int j = 0; j < 4; ++j) {
                        float2 d = make_float2(0.f, 0.f);
                        if (u0 + 2 * j + 1 < U) d = __ldg(&x2[j]);
                        v[2 * j]     = d.x;
                        v[2 * j + 1] = d.y;
                    }
                    float sm = 0.f;
                    #pragma unroll
                    for (int k = 0; k < 8; ++k) {
                        float e = (u0 + k < tl) ? __expf(v[k] + 1.f) : 0.f;
                        v[k] = e;
                        sm += e;
                    }
                    #pragma unroll
                    for (int off = 16; off; off >>= 1)
                        sm += __shfl_xor_sync(FULLM, sm, off);
                    if (row < ml)
                        zacc += (double)(__logf(sm + 1.f) - 1.f);
                    float4* dst = (float4*)(stg + (size_t)(8 * h + w) * 1024);
                    dst[lane]      = make_float4(v[0], v[4], v[1], v[5]);
                    dst[32 + lane] = make_float4(v[2], v[6], v[3], v[7]);
                }
            }
            __syncwarp();
            if (lane == 0) mbar_arrive(full_a + 8u * slot);
            if (++slot == NSLOT) { slot = 0; ++rnd; }
        }
        if (lane == 0) szs[w] = zacc;
        __syncthreads();                       // matches consumer's barrier
    } else {
        // ---------------- consumer warp: blocked-FP scan ----------------
        ull E[4] = {0ull,0ull,0ull,0ull}, O[4] = {0ull,0ull,0ull,0ull};
        if (lane == 0) E[0] = packx2(1.f, 0.f);   // state 0 = 1
        int   G = 0, Gcap = 0;
        float fincap = 0.f;
        float f = (lane == 0) ? 0.f : 1.f;
        float prevS = 0.f, raw;

        int slot = 0, rnd = 0;
        for (int i = 0; i < full; ++i) {
            mbar_wait(full_a + 8u * slot, rnd & 1);
            const uint32_t sb = sdyn_a + slot * STGB + lane * 16u;
            ulonglong2 c0 = lds128(sb), c1 = lds128(sb + 512u);
            #pragma unroll
            for (int r = 0; r < 16; ++r) {
                ulonglong2 n0, n1;
                if (r < 15) {
                    n0 = lds128(sb + (r + 1) * 1024u);
                    n1 = lds128(sb + (r + 1) * 1024u + 512u);
                }
                stepP(E, O, c0, c1, prevS, raw);
                prevS = raw * f;
                if (r == 7) {
                    FS_RENORM();
                    prevS = __shfl_up_sync(FULLM, hix2(O[3]), 1) * f;
                }
                if (r < 15) { c0 = n0; c1 = n1; }
            }
            FS_RENORM();
            prevS = __shfl_up_sync(FULLM, hix2(O[3]), 1) * f;
            __syncwarp();
            if (lane == 0) mbar_arrive(empty_a + 8u * slot);
            if (++slot == NSLOT) { slot = 0; ++rnd; }
        }
        {   // tail: steps 16*full .. mlm1 (rem+1 steps)
            mbar_wait(full_a + 8u * slot, rnd & 1);
            const uint32_t sb = sdyn_a + slot * STGB + lane * 16u;
            #pragma unroll
            for (int r = 0; r < 16; ++r) {
                ulonglong2 c0 = lds128(sb + r * 1024u);
                ulonglong2 c1 = lds128(sb + r * 1024u + 512u);
                stepS(E, O, c0, c1, f);
                if (r == rem) { FS_CAPTURE(); break; }
                if (r == 7) FS_RENORM();
            }
        }
        __syncthreads();                       // producers' szs now visible

        // lse over lanes (up to 2 lanes hold fin terms, own exponents each)
        double lv = (fincap > 0.f)
            ? (log((double)fincap) + (double)Gcap * LN2D) : -1e300;
        double mx = lv;
        #pragma unroll
        for (int off = 16; off; off >>= 1)
            mx = fmax(mx, __shfl_xor_sync(FULLM, mx, off));
        double ex = (lv > -1e299) ? exp(lv - mx) : 0.0;
        #pragma unroll
        for (int off = 16; off; off >>= 1)
            ex += __shfl_xor_sync(FULLM, ex, off);

        if (lane == 0) {
            double zs = 0.0;
            #pragma unroll
            for (int p = 0; p < NPREP; ++p) zs += szs[p];
            float loss = 0.f;
            if (mx > -1e299) {
                double fin = (mx + log(ex)) - (double)ml - zs;
                loss = (float)(-fin / (double)tl);
            }
            g_loss[b] = loss;
            __threadfence();
            int ticket = atomicAdd(&g_done, 1);
            if (ticket == Bn - 1) {          // last CTA reduces (fixed order)
                float sacc = 0.f;
                for (int i = 0; i < Bn; ++i) sacc += g_loss[i];
                out[0] = sacc / (float)Bn;
                g_done = 0;                  // reset for next launch
            }
        }
    }
}

extern "C" void kernel_launch(void* const* d_in, const int* in_sizes, int n_in,
                              void* d_out, int out_size)
{
    const float* attn = (const float*)d_in[0];
    const int*   tl   = (const int*)d_in[1];
    const int*   ml   = (const int*)d_in[2];
    int B = in_sizes[1];
    const int U = 250;
    int T = in_sizes[0] / (B * U);

    cudaFuncSetAttribute(fsloss_fused,
                         cudaFuncAttributeMaxDynamicSharedMemorySize,
                         NSLOT * (int)STGB);

    fsloss_fused<<<B, 288, NSLOT * STGB>>>(attn, tl, ml, T, U, (float*)d_out);
}

// round 17
// speedup vs baseline: 1.2729x; 1.0023x over previous
#include <cuda_runtime.h>
#include <math.h>
#include <stdint.h>

#define FULLM 0xffffffffu
#define BMAX 64
#define NSLOT 5
#define STGB 16384u            // 16 rows x 1KB per stage
#define NPREP 8                // producer warps
#define LN2D 0.6931471805599453

typedef unsigned long long ull;

// Scratch (allocation-free rule: __device__ globals).
__device__ float g_loss[BMAX];
__device__ int   g_done = 0;   // reset by last CTA each launch

// ---- f32x2 packed helpers (Blackwell sm_103a) ------------------------------
__device__ __forceinline__ ull addx2(ull a, ull b) {
    ull r; asm("add.rn.f32x2 %0, %1, %2;" : "=l"(r) : "l"(a), "l"(b)); return r;
}
__device__ __forceinline__ ull mulx2(ull a, ull b) {
    ull r; asm("mul.rn.f32x2 %0, %1, %2;" : "=l"(r) : "l"(a), "l"(b)); return r;
}
__device__ __forceinline__ ull packx2(float lo, float hi) {
    ull r; asm("mov.b64 %0, {%1, %2};" : "=l"(r) : "f"(lo), "f"(hi)); return r;
}
__device__ __forceinline__ float lox2(ull v) {
    float a, b; asm("mov.b64 {%0, %1}, %2;" : "=f"(a), "=f"(b) : "l"(v)); return a;
}
__device__ __forceinline__ float hix2(ull v) {
    float a, b; asm("mov.b64 {%0, %1}, %2;" : "=f"(a), "=f"(b) : "l"(v)); return b;
}
__device__ __forceinline__ uint32_t smem_u32(const void* p) {
    uint32_t a;
    asm("{.reg .u64 t; cvta.to.shared.u64 t, %1; cvt.u32.u64 %0, t;}"
        : "=r"(a) : "l"(p));
    return a;
}
__device__ __forceinline__ ulonglong2 lds128(uint32_t a) {
    ulonglong2 v;
    asm("ld.shared.v2.u64 {%0, %1}, [%2];" : "=l"(v.x), "=l"(v.y) : "r"(a));
    return v;
}
// tight spin (consumer — must wake instantly, almost never waits)
__device__ __forceinline__ void mbar_wait(uint32_t bar, int parity) {
    asm volatile(
        "{\n\t.reg .pred P;\n"
        "W%=:\n\t"
        "mbarrier.try_wait.parity.shared.b64 P, [%0], %1;\n\t"
        "@!P bra W%=;\n\t}"
        :: "r"(bar), "r"(parity) : "memory");
}
// sleepy wait (producers — they idle ~85% of kernel life; spinning here
// steals issue slots from the consumer's SMSP, which was R16's regression)
__device__ __forceinline__ void mbar_wait_sleep(uint32_t bar, int parity) {
    asm volatile(
        "{\n\t.reg .pred P;\n"
        "W%=:\n\t"
        "mbarrier.try_wait.parity.shared.b64 P, [%0], %1;\n\t"
        "@P bra D%=;\n\t"
        "nanosleep.u32 300;\n\t"
        "bra W%=;\n"
        "D%=:\n\t}"
        :: "r"(bar), "r"(parity) : "memory");
}
__device__ __forceinline__ void mbar_arrive(uint32_t bar) {
    asm volatile("mbarrier.arrive.shared.b64 _, [%0];" :: "r"(bar) : "memory");
}

// renorm: exponent from SUM of the lane's 16 values (upper bound on max).
#define FS_RENORM()                                                           \
    do {                                                                      \
        ull sE = addx2(addx2(E[0], E[1]), addx2(E[2], E[3]));                 \
        ull sO = addx2(addx2(O[0], O[1]), addx2(O[2], O[3]));                 \
        ull sA = addx2(sE, sO);                                               \
        float msum = lox2(sA) + hix2(sA);                                     \
        bool nz = (msum > 0.f);                                               \
        if (nz) {                                                             \
            int Ee = (int)((__float_as_uint(msum) >> 23) & 255u);             \
            float sc = __uint_as_float((unsigned)(254 - Ee) << 23);           \
            ull SC = packx2(sc, sc);                                          \
            E[0] = mulx2(E[0], SC); E[1] = mulx2(E[1], SC);                   \
            E[2] = mulx2(E[2], SC); E[3] = mulx2(E[3], SC);                   \
            O[0] = mulx2(O[0], SC); O[1] = mulx2(O[1], SC);                   \
            O[2] = mulx2(O[2], SC); O[3] = mulx2(O[3], SC);                   \
            G += Ee - 127;                                                    \
        }                                                                     \
        int val = (G << 1) | (nz ? 1 : 0);                                    \
        int up  = __shfl_up_sync(FULLM, val, 1);                              \
        int Gup = up >> 1;                                                    \
        if (!nz && lane > 0) G = Gup;                                         \
        int D = Gup - G;                                                      \
        if (D > 127) D = 127;                                                 \
        f = (lane == 0 || !(up & 1) || D < -126) ? 0.f                        \
            : __uint_as_float((unsigned)(D + 127) << 23);                     \
    } while (0)

#define FS_CAPTURE()                                                          \
    do {                                                                      \
        _Pragma("unroll")                                                     \
        for (int k = 0; k < 8; ++k) {                                         \
            float ek = (k < 4) ? lox2(E[k]) : hix2(E[k - 4]);                 \
            float ok = (k < 4) ? lox2(O[k]) : hix2(O[k - 4]);                 \
            int se_ = 16 * lane + 2 * k;                                      \
            if (se_ == S)     fincap += ek;                                   \
            if (se_ == S - 2) fincap += ok;                                   \
        }                                                                     \
        Gcap = G;                                                             \
    } while (0)

// scan step: lane holds E[j]=(e[j],e[j+4]), O[j]=(o[j],o[j+4]) (16 states).
__device__ __forceinline__ void stepP(ull E[4], ull O[4],
                                      ulonglong2 Rlo, ulonglong2 Rhi,
                                      float prevS, float& rawNext)
{
    float o3lo = lox2(O[3]);
    ull S3 = addx2(E[3], O[2]);
    ull T3 = addx2(O[3], S3);
    ull O3n = mulx2(Rhi.y, T3);
    rawNext = __shfl_up_sync(FULLM, hix2(O3n), 1);
    ull S2 = addx2(E[2], O[1]);
    ull T2 = addx2(O[2], S2);
    O[2] = mulx2(Rhi.x, T2); E[2] = S2;
    ull S1 = addx2(E[1], O[0]);
    ull T1 = addx2(O[1], S1);
    O[1] = mulx2(Rlo.y, T1); E[1] = S1;
    ull Osh0 = packx2(prevS, o3lo);
    ull S0 = addx2(E[0], Osh0);
    ull T0 = addx2(O[0], S0);
    O[0] = mulx2(Rlo.x, T0); E[0] = S0;
    O[3] = O3n; E[3] = S3;
}

__device__ __forceinline__ void stepS(ull E[4], ull O[4],
                                      ulonglong2 Rlo, ulonglong2 Rhi, float f)
{
    float prev = __shfl_up_sync(FULLM, hix2(O[3]), 1) * f;
    float o3lo = lox2(O[3]);
    ull S3 = addx2(E[3], O[2]); ull T3 = addx2(O[3], S3);
    O[3] = mulx2(Rhi.y, T3); E[3] = S3;
    ull S2 = addx2(E[2], O[1]); ull T2 = addx2(O[2], S2);
    O[2] = mulx2(Rhi.x, T2); E[2] = S2;
    ull S1 = addx2(E[1], O[0]); ull T1 = addx2(O[1], S1);
    O[1] = mulx2(Rlo.y, T1); E[1] = S1;
    ull Osh0 = packx2(prev, o3lo);
    ull S0 = addx2(E[0], Osh0); ull T0 = addx2(O[0], S0);
    O[0] = mulx2(Rlo.x, T0); E[0] = S0;
}

// ---------------------------------------------------------------------------
// Fused kernel: one CTA per batch. 8 producer warps compute r = exp(x+1) rows
// straight into a 5-stage x 16KB smem ring (interleaved layout) and accumulate
// sum(logZ); 1 consumer warp runs the proven single-warp blocked-FP scan.
// Producers SLEEP while ring-gated (nanosleep backoff) so the consumer's
// SMSP issue slots stay free. Full barriers count NPREP; empty count 1.
// ---------------------------------------------------------------------------
__global__ void __launch_bounds__(288)
fsloss_fused(const float* __restrict__ attn,
             const int* __restrict__ text_lens,
             const int* __restrict__ mel_lens,
             int T, int U, float* __restrict__ out)
{
    extern __shared__ unsigned char sdyn[];
    __shared__ ull    sfull[NSLOT], sempty[NSLOT];
    __shared__ double szs[NPREP];

    const int tid = threadIdx.x, w = tid >> 5, lane = tid & 31;
    const int b  = blockIdx.x;
    const int tl = text_lens[b], ml = mel_lens[b];
    const int S  = 2 * tl, mlm1 = ml - 1;
    const int Bn = gridDim.x;
    const int full = mlm1 >> 4, rem = mlm1 & 15;   // full >= 37 (ml >= 600)

    const uint32_t sdyn_a  = smem_u32(sdyn);
    const uint32_t full_a  = smem_u32(sfull);
    const uint32_t empty_a = smem_u32(sempty);

    if (tid == 0) {
        #pragma unroll
        for (int s = 0; s < NSLOT; ++s) {
            asm volatile("mbarrier.init.shared.b64 [%0], %1;"
                         :: "r"(full_a + 8u * s), "r"(NPREP) : "memory");
            asm volatile("mbarrier.init.shared.b64 [%0], 1;"
                         :: "r"(empty_a + 8u * s) : "memory");
        }
    }
    __syncthreads();

    if (w < NPREP) {
        // ---------------- producer warp w: rows == w (mod 8) ----------------
        const float* xb = attn + (size_t)b * T * U;
        double zacc = 0.0;
        int slot = 0, rnd = 0;
        for (int s = 0; s <= full; ++s) {
            if (rnd) mbar_wait_sleep(empty_a + 8u * slot, (rnd - 1) & 1);
            unsigned char* stg = sdyn + (size_t)slot * STGB;
            #pragma unroll
            for (int h = 0; h < 2; ++h) {
                const int row = 16 * s + 8 * h + w;
                if (row < T) {
                    const int u0 = 8 * lane;
                    const float2* x2 =
                        (const float2*)(xb + (size_t)row * U) + 4 * lane;
                    float v[8];
                    #pragma unroll
                    for (int j = 0; j < 4; ++j) {
                        float2 d = make_float2(0.f, 0.f);
                        if (u0 + 2 * j + 1 < U) d = __ldg(&x2[j]);
                        v[2 * j]     = d.x;
                        v[2 * j + 1] = d.y;
                    }
                    float sm = 0.f;
                    #pragma unroll
                    for (int k = 0; k < 8; ++k) {
                        float e = (u0 + k < tl) ? __expf(v[k] + 1.f) : 0.f;
                        v[k] = e;
                        sm += e;
                    }
                    #pragma unroll
                    for (int off = 16; off; off >>= 1)
                        sm += __shfl_xor_sync(FULLM, sm, off);
                    if (row < ml)
                        zacc += (double)(__logf(sm + 1.f) - 1.f);
                    float4* dst = (float4*)(stg + (size_t)(8 * h + w) * 1024);
                    dst[lane]      = make_float4(v[0], v[4], v[1], v[5]);
                    dst[32 + lane] = make_float4(v[2], v[6], v[3], v[7]);
                }
            }
            __syncwarp();
            if (lane == 0) mbar_arrive(full_a + 8u * slot);
            if (++slot == NSLOT) { slot = 0; ++rnd; }
        }
        if (lane == 0) szs[w] = zacc;
        __syncthreads();                       // matches consumer's barrier
    } else {
        // ---------------- consumer warp: blocked-FP scan ----------------
        ull E[4] = {0ull,0ull,0ull,0ull}, O[4] = {0ull,0ull,0ull,0ull};
        if (lane == 0) E[0] = packx2(1.f, 0.f);   // state 0 = 1
        int   G = 0, Gcap = 0;
        float fincap = 0.f;
        float f = (lane == 0) ? 0.f : 1.f;
        float prevS = 0.f, raw;

        int slot = 0, rnd = 0;
        for (int i = 0; i < full; ++i) {
            mbar_wait(full_a + 8u * slot, rnd & 1);
            const uint32_t sb = sdyn_a + slot * STGB + lane * 16u;
            ulonglong2 c0 = lds128(sb), c1 = lds128(sb + 512u);
            #pragma unroll
            for (int r = 0; r < 16; ++r) {
                ulonglong2 n0, n1;
                if (r < 15) {
                    n0 = lds128(sb + (r + 1) * 1024u);
                    n1 = lds128(sb + (r + 1) * 1024u + 512u);
                }
                stepP(E, O, c0, c1, prevS, raw);
                prevS = raw * f;
                if (r == 7) {
                    FS_RENORM();
                    prevS = __shfl_up_sync(FULLM, hix2(O[3]), 1) * f;
                }
                if (r < 15) { c0 = n0; c1 = n1; }
            }
            FS_RENORM();
            prevS = __shfl_up_sync(FULLM, hix2(O[3]), 1) * f;
            __syncwarp();
            if (lane == 0) mbar_arrive(empty_a + 8u * slot);
            if (++slot == NSLOT) { slot = 0; ++rnd; }
        }
        {   // tail: steps 16*full .. mlm1 (rem+1 steps)
            mbar_wait(full_a + 8u * slot, rnd & 1);
            const uint32_t sb = sdyn_a + slot * STGB + lane * 16u;
            #pragma unroll
            for (int r = 0; r < 16; ++r) {
                ulonglong2 c0 = lds128(sb + r * 1024u);
                ulonglong2 c1 = lds128(sb + r * 1024u + 512u);
                stepS(E, O, c0, c1, f);
                if (r == rem) { FS_CAPTURE(); break; }
                if (r == 7) FS_RENORM();
            }
        }
        __syncthreads();                       // producers' szs now visible

        // lse over lanes (up to 2 lanes hold fin terms, own exponents each)
        double lv = (fincap > 0.f)
            ? (log((double)fincap) + (double)Gcap * LN2D) : -1e300;
        double mx = lv;
        #pragma unroll
        for (int off = 16; off; off >>= 1)
            mx = fmax(mx, __shfl_xor_sync(FULLM, mx, off));
        double ex = (lv > -1e299) ? exp(lv - mx) : 0.0;
        #pragma unroll
        for (int off = 16; off; off >>= 1)
            ex += __shfl_xor_sync(FULLM, ex, off);

        if (lane == 0) {
            double zs = 0.0;
            #pragma unroll
            for (int p = 0; p < NPREP; ++p) zs += szs[p];
            float loss = 0.f;
            if (mx > -1e299) {
                double fin = (mx + log(ex)) - (double)ml - zs;
                loss = (float)(-fin / (double)tl);
            }
            g_loss[b] = loss;
            __threadfence();
            int ticket = atomicAdd(&g_done, 1);
            if (ticket == Bn - 1) {          // last CTA reduces (fixed order)
                float sacc = 0.f;
                for (int i = 0; i < Bn; ++i) sacc += g_loss[i];
                out[0] = sacc / (float)Bn;
                g_done = 0;                  // reset for next launch
            }
        }
    }
}

extern "C" void kernel_launch(void* const* d_in, const int* in_sizes, int n_in,
                              void* d_out, int out_size)
{
    const float* attn = (const float*)d_in[0];
    const int*   tl   = (const int*)d_in[1];
    const int*   ml   = (const int*)d_in[2];
    int B = in_sizes[1];
    const int U = 250;
    int T = in_sizes[0] / (B * U);

    cudaFuncSetAttribute(fsloss_fused,
                         cudaFuncAttributeMaxDynamicSharedMemorySize,
                         NSLOT * (int)STGB);

    fsloss_fused<<<B, 288, NSLOT * STGB>>>(attn, tl, ml, T, U, (float*)d_out);
}